// round 4
// baseline (speedup 1.0000x reference)
#include <cuda_runtime.h>

// ---------------- problem constants ----------------
#define BB   16
#define CC_  128      // in = out channels
#define HH   64
#define WW_  64
#define ZD   128
#define NG   8
#define CPG  16       // channels per group
#define EPSV 1e-5f
#define NW1  (CC_*CC_*9)        // 147456 weights per sample per conv
#define IMG  (CC_*HH*WW_)       // 524288 elems per sample
#define GRPN (CPG*HH*WW_)       // 65536 elems per (b,group)

// ---------------- scratch (alloc-free) ----------------
__device__ float g_w1[BB*NW1];      // per-sample conv1 weights
__device__ float g_w2[BB*NW1];      // per-sample conv2 weights
__device__ float g_buf1[BB*IMG];    // conv1 raw output
__device__ float g_buf2[BB*IMG];    // conv2 raw output
__device__ float g_stats1[BB*NG*2]; // sum, sumsq
__device__ float g_stats2[BB*NG*2];
__device__ float g_mi1[BB*NG*2];    // mean, rsqrt(var+eps)
__device__ float g_mi2[BB*NG*2];

// ---------------- init: zero stats ----------------
__global__ void init_stats_kernel() {
    int i = threadIdx.x;            // 256 threads
    g_stats1[i] = 0.f;
    g_stats2[i] = 0.f;
}

// ---------------- hypernet weight generation ----------------
// out[b*NW1 + idx] = dot(z[b,:], hw[:,idx]) + hb[idx]
// grid 576 x 256 threads = 147456 threads (one per idx), 16 batches per thread.
template <int HEAD>
__global__ void gen_w_kernel(const float* __restrict__ z,
                             const float* __restrict__ hw,
                             const float* __restrict__ hb) {
    __shared__ float zs[BB*ZD];
    int tid = threadIdx.x;
    for (int e = tid; e < BB*ZD; e += 256) zs[e] = z[e];
    __syncthreads();

    int idx = blockIdx.x * 256 + tid;      // < 147456 exactly
    float* out = (HEAD == 0) ? g_w1 : g_w2;

    float bias = hb[idx];
    float acc[BB];
#pragma unroll
    for (int b = 0; b < BB; b++) acc[b] = bias;

    for (int zd = 0; zd < ZD; zd++) {
        float v = hw[zd * NW1 + idx];       // coalesced across threads
#pragma unroll
        for (int b = 0; b < BB; b++)
            acc[b] = fmaf(zs[b * ZD + zd], v, acc[b]);  // zs read is broadcast
    }
#pragma unroll
    for (int b = 0; b < BB; b++) out[(size_t)b * NW1 + idx] = acc[b];
}

// ---------------- direct conv, tiled ----------------
// Block: 32 out-ch x (8 x 16) spatial tile for one sample.
// Threads (256): tx = tid&3 (4-px column group), ty = (tid>>2)&7 (row),
//                og = tid>>5 (4-channel group) -> one warp = one og (weight
//                smem loads are warp-uniform broadcasts; stats reduce in-warp).
// PASS 0: input = x (raw).  PASS 1: input = g_buf1, GN1+ReLU applied on load.
template <int PASS>
__global__ __launch_bounds__(256) void conv_kernel(
        const float* __restrict__ xin,
        const float* __restrict__ gamma,   // gamma of the *input* norm (PASS1)
        const float* __restrict__ beta) {
    __shared__ float xs[16][10][19];       // ci-chunk x (8+2) x (16+2) (+pad)
    __shared__ float ws[32][144];          // 32 o x (16 ci * 9)

    const float* in  = (PASS == 0) ? xin     : g_buf1;
    const float* w   = (PASS == 0) ? g_w1    : g_w2;
    float*       out = (PASS == 0) ? g_buf1  : g_buf2;
    float*       st  = (PASS == 0) ? g_stats1: g_stats2;
    const float* mi  = g_mi1;

    const int tid = threadIdx.x;
    const int xg  = tid & 3;
    const int ty  = (tid >> 2) & 7;
    const int og  = tid >> 5;

    const int sp  = blockIdx.x;            // 0..31 spatial tile
    const int cob = blockIdx.y * 32;       // out-channel base
    const int b   = blockIdx.z;            // sample
    const int y0  = (sp >> 2) * 8;
    const int x0  = (sp & 3) * 16;

    const float* inb = in + (size_t)b * IMG;
    const float* wb  = w  + (size_t)b * NW1;

    float acc[4][4];
#pragma unroll
    for (int j = 0; j < 4; j++)
#pragma unroll
        for (int i = 0; i < 4; i++) acc[j][i] = 0.f;

    for (int cc = 0; cc < CC_; cc += 16) {
        // ---- load input tile (zero-padded borders; PASS1: GN1+ReLU fused) ----
        for (int e = tid; e < 16 * 10 * 18; e += 256) {
            int ci = e / 180;
            int r  = e % 180;
            int ly = r / 18, lx = r % 18;
            int gy = y0 + ly - 1, gx = x0 + lx - 1;
            float v = 0.f;
            int c = cc + ci;
            if (gy >= 0 && gy < 64 && gx >= 0 && gx < 64) {
                v = inb[((size_t)c * 64 + gy) * 64 + gx];
                if (PASS == 1) {
                    int mg = (b * NG + (c >> 4)) * 2;
                    float n = (v - mi[mg]) * mi[mg + 1];
                    v = fmaxf(fmaf(n, gamma[c], beta[c]), 0.f);
                }
            }
            xs[ci][ly][lx] = v;
        }
        // ---- load weight tile ----
        for (int e = tid; e < 32 * 144; e += 256) {
            int ol = e / 144, r = e % 144;
            ws[ol][r] = wb[(size_t)(cob + ol) * (CC_ * 9) + cc * 9 + r];
        }
        __syncthreads();

        // ---- compute ----
        for (int ci = 0; ci < 16; ci++) {
#pragma unroll
            for (int ky = 0; ky < 3; ky++) {
                float xr[6];
#pragma unroll
                for (int i = 0; i < 6; i++) xr[i] = xs[ci][ty + ky][xg * 4 + i];
#pragma unroll
                for (int kx = 0; kx < 3; kx++) {
#pragma unroll
                    for (int j = 0; j < 4; j++) {
                        float wv = ws[og * 4 + j][ci * 9 + ky * 3 + kx]; // broadcast
#pragma unroll
                        for (int i = 0; i < 4; i++)
                            acc[j][i] = fmaf(wv, xr[kx + i], acc[j][i]);
                    }
                }
            }
        }
        __syncthreads();
    }

    // ---- store (vectorized) + per-warp group-norm partial stats ----
    float s = 0.f, sq = 0.f;
#pragma unroll
    for (int j = 0; j < 4; j++) {
        int o = cob + og * 4 + j;
        float4 v4 = make_float4(acc[j][0], acc[j][1], acc[j][2], acc[j][3]);
        *(float4*)&out[(((size_t)b * CC_ + o) * 64 + y0 + ty) * 64 + x0 + xg * 4] = v4;
#pragma unroll
        for (int i = 0; i < 4; i++) { float v = acc[j][i]; s += v; sq += v * v; }
    }
#pragma unroll
    for (int off = 16; off; off >>= 1) {
        s  += __shfl_down_sync(0xffffffffu, s,  off);
        sq += __shfl_down_sync(0xffffffffu, sq, off);
    }
    if ((tid & 31) == 0) {                  // whole warp shares one group
        int g = (cob + og * 4) >> 4;
        atomicAdd(&st[(b * NG + g) * 2],     s);
        atomicAdd(&st[(b * NG + g) * 2 + 1], sq);
    }
}

// ---------------- finalize group stats ----------------
template <int PASS>
__global__ void finalize_kernel() {
    const float* st = (PASS == 0) ? g_stats1 : g_stats2;
    float*       mi = (PASS == 0) ? g_mi1    : g_mi2;
    int i = threadIdx.x;                    // 128 = 16 b * 8 g
    float sum = st[i * 2], sq = st[i * 2 + 1];
    const float invN = 1.f / (float)GRPN;
    float mean = sum * invN;
    float var  = sq * invN - mean * mean;
    mi[i * 2]     = mean;
    mi[i * 2 + 1] = rsqrtf(var + EPSV);
}

// ---------------- epilogue: GN2 + residual + ReLU ----------------
__global__ void epilogue_kernel(const float* __restrict__ x,
                                const float* __restrict__ gamma,
                                const float* __restrict__ beta,
                                float* __restrict__ out) {
    int i = blockIdx.x * 256 + threadIdx.x;   // 8388608 elements
    int c = (i >> 12) & 127;
    int b = i >> 19;
    int mg = (b * NG + (c >> 4)) * 2;
    float v = (g_buf2[i] - g_mi2[mg]) * g_mi2[mg + 1];
    v = fmaf(v, gamma[c], beta[c]) + x[i];
    out[i] = fmaxf(v, 0.f);
}

// ---------------- launch ----------------
extern "C" void kernel_launch(void* const* d_in, const int* in_sizes, int n_in,
                              void* d_out, int out_size) {
    const float* x   = (const float*)d_in[0];
    const float* z   = (const float*)d_in[1];
    const float* h1w = (const float*)d_in[2];
    const float* h1b = (const float*)d_in[3];
    const float* h2w = (const float*)d_in[4];
    const float* h2b = (const float*)d_in[5];
    const float* g1  = (const float*)d_in[6];
    const float* b1  = (const float*)d_in[7];
    const float* g2  = (const float*)d_in[8];
    const float* b2  = (const float*)d_in[9];
    float* out = (float*)d_out;

    init_stats_kernel<<<1, 256>>>();
    gen_w_kernel<0><<<NW1 / 256, 256>>>(z, h1w, h1b);
    gen_w_kernel<1><<<NW1 / 256, 256>>>(z, h2w, h2b);

    dim3 cgrid(32, 4, 16);                  // spatial, co-tiles, batch
    conv_kernel<0><<<cgrid, 256>>>(x, g1, b1);   // gamma/beta unused in PASS0
    finalize_kernel<0><<<1, 128>>>();
    conv_kernel<1><<<cgrid, 256>>>(x, g1, b1);   // applies GN1+ReLU on load
    finalize_kernel<1><<<1, 128>>>();
    epilogue_kernel<<<(BB * IMG) / 256, 256>>>(x, g2, b2, out);
}

// round 5
// speedup vs baseline: 1.2900x; 1.2900x over previous
#include <cuda_runtime.h>

// ---------------- problem constants ----------------
#define BB   16
#define CC_  128
#define HH   64
#define WW_  64
#define ZD   128
#define NG   8
#define CPG  16
#define EPSV 1e-5f
#define NW1  (CC_*CC_*9)        // 147456
#define IMG  (CC_*HH*WW_)       // 524288
#define GRPN (CPG*HH*WW_)       // 65536

typedef unsigned long long ull;

// packed fp32x2 FMA (SASS FFMA2): d = a*b + d elementwise on two fp32 lanes
#define FMA2(d,a,b) asm("fma.rn.f32x2 %0, %1, %2, %0;" : "+l"(d) : "l"(a), "l"(b))

// ---------------- scratch (alloc-free) ----------------
__device__ float g_w1[BB*NW1];      // hypernet out, [b][oc][1152]
__device__ float g_w2[BB*NW1];
__device__ float g_wt1[BB*NW1];     // transposed,   [b][1152][oc]
__device__ float g_wt2[BB*NW1];
__device__ float g_buf1[BB*IMG];
__device__ float g_buf2[BB*IMG];
__device__ float g_stats1[BB*NG*2];
__device__ float g_stats2[BB*NG*2];
__device__ float g_mi1[BB*NG*2];
__device__ float g_mi2[BB*NG*2];

// ---------------- init: zero stats ----------------
__global__ void init_stats_kernel() {
    int i = threadIdx.x;
    g_stats1[i] = 0.f;
    g_stats2[i] = 0.f;
}

// ---------------- hypernet weight generation ----------------
template <int HEAD>
__global__ void gen_w_kernel(const float* __restrict__ z,
                             const float* __restrict__ hw,
                             const float* __restrict__ hb) {
    __shared__ float zs[BB*ZD];
    int tid = threadIdx.x;
    for (int e = tid; e < BB*ZD; e += 256) zs[e] = z[e];
    __syncthreads();

    int idx = blockIdx.x * 256 + tid;
    float* out = (HEAD == 0) ? g_w1 : g_w2;

    float bias = hb[idx];
    float acc[BB];
#pragma unroll
    for (int b = 0; b < BB; b++) acc[b] = bias;

    for (int zd = 0; zd < ZD; zd++) {
        float v = hw[zd * NW1 + idx];
#pragma unroll
        for (int b = 0; b < BB; b++)
            acc[b] = fmaf(zs[b * ZD + zd], v, acc[b]);
    }
#pragma unroll
    for (int b = 0; b < BB; b++) out[(size_t)b * NW1 + idx] = acc[b];
}

// ---------------- weight transpose: [b][128oc][1152] -> [b][1152][128oc] ----
__global__ void transpose_w_kernel() {
    __shared__ float t[32][33];
    int r0 = blockIdx.x * 32;           // 36 tiles over 1152
    int o0 = blockIdx.y * 32;           // 4 tiles over 128
    int bz = blockIdx.z;                // 32 = b*2 + head
    const float* src = (bz & 1) ? g_w2 : g_w1;
    float*       dst = (bz & 1) ? g_wt2 : g_wt1;
    int b = bz >> 1;
    int tx = threadIdx.x & 31, ty = threadIdx.x >> 5;   // 32 x 8
#pragma unroll
    for (int k = 0; k < 4; k++)
        t[ty + 8*k][tx] = src[(size_t)b * NW1 + (size_t)(o0 + ty + 8*k) * 1152 + r0 + tx];
    __syncthreads();
#pragma unroll
    for (int k = 0; k < 4; k++)
        dst[(size_t)b * NW1 + (size_t)(r0 + ty + 8*k) * 128 + o0 + tx] = t[tx][ty + 8*k];
}

// ---------------- direct conv, FFMA2 packed over oc pairs ----------------
// Block tile: 32 oc x 16 x 16 pixels, one sample.
// Thread: 8 oc (4 f32x2 pairs) x 1 row x 4 cols.
//   xg = tid&3 (col group), trow = (tid>>2)&15 (row), ocg = tid>>6 (warp-uniform).
// x operand stored DUPLICATED (v,v) as float2 -> FMA2 x-broadcast with zero packs.
// Weights oc-contiguous -> LDS.128 broadcast gives two oc-pairs per load.
template <int PASS>
__global__ __launch_bounds__(256, 3) void conv_kernel(
        const float* __restrict__ xin,
        const float* __restrict__ gamma,
        const float* __restrict__ beta) {
    __shared__ alignas(16) float2 xs[16][18][18];   // ci x (16+2) x (16+2), dup
    __shared__ alignas(16) float  ws[16][9][32];    // ci x kk x oc (contig)

    const float* in  = PASS ? g_buf1  : xin;
    const float* w   = PASS ? g_wt2   : g_wt1;
    float*       out = PASS ? g_buf2  : g_buf1;
    float*       st  = PASS ? g_stats2: g_stats1;

    const int tid  = threadIdx.x;
    const int xg   = tid & 3;
    const int trow = (tid >> 2) & 15;
    const int ocg  = tid >> 6;

    const int sp  = blockIdx.x;                // 16 spatial tiles (4x4 of 16x16)
    const int cob = blockIdx.y * 32;
    const int b   = blockIdx.z;
    const int y0  = (sp >> 2) * 16;
    const int x0  = (sp & 3) * 16;

    const float* inb = in + (size_t)b * IMG;
    float* wsf = &ws[0][0][0];

    ull acc[4][4];
#pragma unroll
    for (int j = 0; j < 4; j++)
#pragma unroll
        for (int c = 0; c < 4; c++) acc[j][c] = 0ull;

    for (int cc = 0; cc < CC_; cc += 16) {
        // ---- input tile (zero-pad halo; PASS1: GN1+ReLU fused), dup stores ----
        for (int e = tid; e < 16 * 324; e += 256) {
            int ci = e / 324;
            int rr = e % 324;
            int ly = rr / 18, lx = rr % 18;
            int gy = y0 + ly - 1, gx = x0 + lx - 1;
            float v = 0.f;
            if ((unsigned)gy < 64u && (unsigned)gx < 64u) {
                int c = cc + ci;
                v = inb[((size_t)c << 12) + (gy << 6) + gx];
                if (PASS == 1) {
                    int mg = (b * NG + (c >> 4)) * 2;
                    float n = (v - g_mi1[mg]) * g_mi1[mg + 1];
                    v = fmaxf(fmaf(n, gamma[c], beta[c]), 0.f);
                }
            }
            xs[ci][ly][lx] = make_float2(v, v);
        }
        // ---- weight tile: oc-fastest, fully coalesced both sides ----
        {
            const float* wb = w + ((size_t)b * 1152 + cc * 9) * 128 + cob;
            for (int e = tid; e < 4608; e += 256) {
                int rr = e >> 5, oc = e & 31;
                wsf[e] = wb[(size_t)rr * 128 + oc];
            }
        }
        __syncthreads();

        // ---- compute: 144 FMA2 + 27 LDS per ci-slice per thread ----
        for (int ci = 0; ci < 16; ci++) {
#pragma unroll
            for (int ky = 0; ky < 3; ky++) {
                const float2* xr = &xs[ci][trow + ky][xg * 4];
                ulonglong2 x01 = *(const ulonglong2*)(xr);
                ulonglong2 x23 = *(const ulonglong2*)(xr + 2);
                ulonglong2 x45 = *(const ulonglong2*)(xr + 4);
                ull xv[6] = {x01.x, x01.y, x23.x, x23.y, x45.x, x45.y};
#pragma unroll
                for (int kx = 0; kx < 3; kx++) {
                    const float* wp = &ws[ci][ky * 3 + kx][ocg * 8];
                    ulonglong2 w0 = *(const ulonglong2*)(wp);      // (oc0,oc1)(oc2,oc3)
                    ulonglong2 w1 = *(const ulonglong2*)(wp + 4);  // (oc4,oc5)(oc6,oc7)
#pragma unroll
                    for (int c = 0; c < 4; c++) {
                        FMA2(acc[0][c], w0.x, xv[kx + c]);
                        FMA2(acc[1][c], w0.y, xv[kx + c]);
                        FMA2(acc[2][c], w1.x, xv[kx + c]);
                        FMA2(acc[3][c], w1.y, xv[kx + c]);
                    }
                }
            }
        }
        __syncthreads();
    }

    // ---- store (float4 per oc) + warp-local group-norm partial stats ----
    const int y = y0 + trow, xb = x0 + xg * 4;
    float s = 0.f, sq = 0.f;
#pragma unroll
    for (int jp = 0; jp < 4; jp++) {
        float lo[4], hi[4];
#pragma unroll
        for (int c = 0; c < 4; c++) {
            float2 f = *(float2*)&acc[jp][c];
            lo[c] = f.x; hi[c] = f.y;
            s  += f.x + f.y;
            sq += f.x * f.x + f.y * f.y;
        }
        int oc0 = cob + ocg * 8 + jp * 2;
        *(float4*)&out[(((size_t)b * CC_ + oc0)     << 12) + (y << 6) + xb] =
            make_float4(lo[0], lo[1], lo[2], lo[3]);
        *(float4*)&out[(((size_t)b * CC_ + oc0 + 1) << 12) + (y << 6) + xb] =
            make_float4(hi[0], hi[1], hi[2], hi[3]);
    }
#pragma unroll
    for (int off = 16; off; off >>= 1) {
        s  += __shfl_down_sync(0xffffffffu, s,  off);
        sq += __shfl_down_sync(0xffffffffu, sq, off);
    }
    if ((tid & 31) == 0) {                  // warp's 8 oc lie in one group
        int g = (cob + ocg * 8) >> 4;
        atomicAdd(&st[(b * NG + g) * 2],     s);
        atomicAdd(&st[(b * NG + g) * 2 + 1], sq);
    }
}

// ---------------- finalize group stats ----------------
template <int PASS>
__global__ void finalize_kernel() {
    const float* st = (PASS == 0) ? g_stats1 : g_stats2;
    float*       mi = (PASS == 0) ? g_mi1    : g_mi2;
    int i = threadIdx.x;                    // 128 = 16 b * 8 g
    float sum = st[i * 2], sq = st[i * 2 + 1];
    const float invN = 1.f / (float)GRPN;
    float mean = sum * invN;
    float var  = sq * invN - mean * mean;
    mi[i * 2]     = mean;
    mi[i * 2 + 1] = rsqrtf(var + EPSV);
}

// ---------------- epilogue: GN2 + residual + ReLU (float4) ----------------
__global__ void epilogue_kernel(const float* __restrict__ x,
                                const float* __restrict__ gamma,
                                const float* __restrict__ beta,
                                float* __restrict__ out) {
    int i4  = blockIdx.x * 256 + threadIdx.x;   // 2097152 vec4 elements
    int idx = i4 * 4;
    int c = (idx >> 12) & 127;
    int b = idx >> 19;
    int mg = (b * NG + (c >> 4)) * 2;
    float mean = g_mi2[mg], inv = g_mi2[mg + 1];
    float ga = gamma[c], be = beta[c];
    float4 v  = *(const float4*)&g_buf2[idx];
    float4 xi = *(const float4*)&x[idx];
    float4 r;
    r.x = fmaxf(fmaf((v.x - mean) * inv, ga, be) + xi.x, 0.f);
    r.y = fmaxf(fmaf((v.y - mean) * inv, ga, be) + xi.y, 0.f);
    r.z = fmaxf(fmaf((v.z - mean) * inv, ga, be) + xi.z, 0.f);
    r.w = fmaxf(fmaf((v.w - mean) * inv, ga, be) + xi.w, 0.f);
    *(float4*)&out[idx] = r;
}

// ---------------- launch ----------------
extern "C" void kernel_launch(void* const* d_in, const int* in_sizes, int n_in,
                              void* d_out, int out_size) {
    const float* x   = (const float*)d_in[0];
    const float* z   = (const float*)d_in[1];
    const float* h1w = (const float*)d_in[2];
    const float* h1b = (const float*)d_in[3];
    const float* h2w = (const float*)d_in[4];
    const float* h2b = (const float*)d_in[5];
    const float* g1  = (const float*)d_in[6];
    const float* b1  = (const float*)d_in[7];
    const float* g2  = (const float*)d_in[8];
    const float* b2  = (const float*)d_in[9];
    float* out = (float*)d_out;

    init_stats_kernel<<<1, 256>>>();
    gen_w_kernel<0><<<NW1 / 256, 256>>>(z, h1w, h1b);
    gen_w_kernel<1><<<NW1 / 256, 256>>>(z, h2w, h2b);

    dim3 tgrid(36, 4, 32);                  // r-tiles, o-tiles, b*2+head
    transpose_w_kernel<<<tgrid, 256>>>();

    dim3 cgrid(16, 4, 16);                  // spatial, oc-tiles, batch
    conv_kernel<0><<<cgrid, 256>>>(x, g1, b1);
    finalize_kernel<0><<<1, 128>>>();
    conv_kernel<1><<<cgrid, 256>>>(x, g1, b1);
    finalize_kernel<1><<<1, 128>>>();
    epilogue_kernel<<<(BB * IMG) / 1024, 256>>>(x, g2, b2, out);
}

// round 10
// speedup vs baseline: 2.4316x; 1.8849x over previous
#include <cuda_runtime.h>
#include <cuda_bf16.h>
#include <cstdint>

// ---------------- problem constants ----------------
#define BB   16
#define CC_  128
#define ZD   128
#define NG   8
#define EPSV 1e-5f
#define NW1  (CC_*CC_*9)        // 147456
#define IMG  (CC_*64*64)        // 524288
#define GRPN (16*64*64)         // 65536

// ---------------- scratch (alloc-free) ----------------
__device__ float g_w1[BB*NW1];      // hypernet out, [b][oc][ci*9+pos]
__device__ float g_w2[BB*NW1];
__device__ float g_wp1[BB*NW1];     // permuted,     [b][oc][pos*128+ci]
__device__ float g_wp2[BB*NW1];
__device__ float g_buf1[BB*IMG];
__device__ float g_buf2[BB*IMG];
__device__ float g_stats1[BB*NG*2];
__device__ float g_stats2[BB*NG*2];
__device__ float g_mi1[BB*NG*2];
__device__ float g_mi2[BB*NG*2];

// ---------------- mma.sync / ldmatrix helpers (sm_80 baseline PTX) --------
__device__ __forceinline__ uint32_t smem_u32(const void* p) {
    uint32_t a;
    asm("{ .reg .u64 t; cvta.to.shared.u64 t, %1; cvt.u32.u64 %0, t; }" : "=r"(a) : "l"(p));
    return a;
}

#define LDSM4(r, addr)                                                        \
    asm volatile("ldmatrix.sync.aligned.m8n8.x4.shared.b16 {%0,%1,%2,%3}, [%4];" \
        : "=r"((r)[0]), "=r"((r)[1]), "=r"((r)[2]), "=r"((r)[3]) : "r"(addr))

#define MMA16816(d, a, b0, b1)                                                \
    asm volatile("mma.sync.aligned.m16n8k16.row.col.f32.bf16.bf16.f32 "       \
        "{%0,%1,%2,%3}, {%4,%5,%6,%7}, {%8,%9}, {%0,%1,%2,%3};"               \
        : "+f"((d)[0]), "+f"((d)[1]), "+f"((d)[2]), "+f"((d)[3])              \
        : "r"((a)[0]), "r"((a)[1]), "r"((a)[2]), "r"((a)[3]), "r"(b0), "r"(b1))

__device__ __forceinline__ uint32_t pack_bf16(float a, float b) {
    unsigned short la = __bfloat16_as_ushort(__float2bfloat16_rn(a));
    unsigned short lb = __bfloat16_as_ushort(__float2bfloat16_rn(b));
    return (uint32_t)la | ((uint32_t)lb << 16);
}

// ---------------- init: zero stats ----------------
__global__ void init_stats_kernel() {
    int i = threadIdx.x;
    g_stats1[i] = 0.f;
    g_stats2[i] = 0.f;
}

// ---------------- hypernet weight generation (float4) ----------------
template <int HEAD>
__global__ __launch_bounds__(256) void gen_w_kernel(const float* __restrict__ z,
                                                    const float* __restrict__ hw,
                                                    const float* __restrict__ hb) {
    __shared__ float zs[BB*ZD];
    int tid = threadIdx.x;
    for (int e = tid; e < BB*ZD; e += 256) zs[e] = z[e];
    __syncthreads();

    int idx4 = (blockIdx.x * 256 + tid) * 4;       // grid 144 -> 147456
    float* out = (HEAD == 0) ? g_w1 : g_w2;

    float4 bias = *(const float4*)&hb[idx4];
    float acc[BB][4];
#pragma unroll
    for (int b = 0; b < BB; b++) {
        acc[b][0] = bias.x; acc[b][1] = bias.y; acc[b][2] = bias.z; acc[b][3] = bias.w;
    }
#pragma unroll 2
    for (int zd = 0; zd < ZD; zd++) {
        float4 v = *(const float4*)&hw[(size_t)zd * NW1 + idx4];
#pragma unroll
        for (int b = 0; b < BB; b++) {
            float zv = zs[b * ZD + zd];
            acc[b][0] = fmaf(zv, v.x, acc[b][0]);
            acc[b][1] = fmaf(zv, v.y, acc[b][1]);
            acc[b][2] = fmaf(zv, v.z, acc[b][2]);
            acc[b][3] = fmaf(zv, v.w, acc[b][3]);
        }
    }
#pragma unroll
    for (int b = 0; b < BB; b++)
        *(float4*)&out[(size_t)b * NW1 + idx4] =
            make_float4(acc[b][0], acc[b][1], acc[b][2], acc[b][3]);
}

// ---------------- K-permute: [b][oc][ci*9+pos] -> [b][oc][pos*128+ci] ------
__global__ void permute_w_kernel() {
    __shared__ float sm[1152];
    int row  = blockIdx.x;                 // 2048 = b*128 + oc
    int head = blockIdx.y;
    const float* src = (head ? g_w2 : g_w1) + (size_t)row * 1152;
    float*       dst = (head ? g_wp2 : g_wp1) + (size_t)row * 1152;
    int tid = threadIdx.x;
    for (int e = tid; e < 1152; e += 256) sm[e] = src[e];
    __syncthreads();
    for (int e = tid; e < 1152; e += 256)
        dst[e] = sm[(e & 127) * 9 + (e >> 7)];   // ci=e&127, pos=e>>7
}

// ---------------- mma.sync bf16x3 implicit-GEMM conv ----------------
// CTA: one sample, 128 px (2 rows x 64 cols) x all 128 oc.
// K = 1152 permuted (pos*128+ci); 36 chunks of 32 ci at fixed pos.
// SMEM rows: 144B stride = [32 bf16 hi | 32 bf16 lo | 16B pad]. Stride 36
// words ≡ 4 (mod 32) -> both STS.128 and LDSM achieve the 4-phase minimum.
// Warp grid 2(M)x4(N); warp tile 64px x 32oc; D = Ah*Bh + Ah*Bl + Al*Bh.
#define SROW 144

template <int PASS>
__global__ __launch_bounds__(256, 2) void conv_mma_kernel(
        const float* __restrict__ xin,
        const float* __restrict__ gamma,
        const float* __restrict__ beta) {
    __shared__ char smA[128 * SROW];
    __shared__ char smB[128 * SROW];

    const float* in   = PASS ? g_buf1  : xin;
    const float* wsrc = PASS ? g_wp2   : g_wp1;
    float*       out  = PASS ? g_buf2  : g_buf1;
    float*       st   = PASS ? g_stats2: g_stats1;

    const int tid  = threadIdx.x;
    const int lane = tid & 31;
    const int wid  = tid >> 5;
    const int wm   = wid & 1;             // M warp group (0..1) -> 64 px
    const int wn   = wid >> 1;            // N warp group (0..3) -> 32 oc
    const int b    = blockIdx.y;
    const int y0   = blockIdx.x * 2;

    const int p     = tid & 127;          // px row of A tile this thread fills
    const int halfk = tid >> 7;           // which 16-ci half
    const int ply   = p >> 6, plx = p & 63;

    const float* inb = in + ((size_t)b << 19);
    const float* wb  = wsrc + (size_t)(b * CC_) * 1152;

    const uint32_t sA = smem_u32(smA);
    const uint32_t sB = smem_u32(smB);

    // ldmatrix per-lane address offsets (bytes)
    const uint32_t aoff = (uint32_t)(lane & 15) * SROW + ((lane >> 4) << 4);
    const uint32_t boff = (uint32_t)((lane & 7) + ((lane >> 3) & 2) * 4) * SROW
                        + (((lane >> 3) & 1) << 4);

    float d[4][4][4];
#pragma unroll
    for (int mi = 0; mi < 4; mi++)
#pragma unroll
        for (int ni = 0; ni < 4; ni++)
#pragma unroll
            for (int k = 0; k < 4; k++) d[mi][ni][k] = 0.f;

    for (int cc = 0; cc < 36; cc++) {
        const int cig = cc / 9, pos = cc % 9;
        const int ci0 = cig * 32;
        const int dy = pos / 3 - 1, dx = pos % 3 - 1;

        // ================= load & split phase =================
        // ---- A: this thread fills 16 ci for px p ----
        {
            int gy = y0 + ply + dy, gx = plx + dx;
            bool ok = ((unsigned)gy < 64u) & ((unsigned)gx < 64u);
            int cib = ci0 + halfk * 16;
            const float* src = inb + ((size_t)cib << 12) + (gy << 6) + gx;
            float va[16];
            if (PASS == 1) {
                int mg = (b * NG + (cib >> 4)) * 2;    // one group per 16 ci
                float mean = g_mi1[mg], inv = g_mi1[mg + 1];
#pragma unroll
                for (int j = 0; j < 16; j++) {
                    float v = ok ? __ldg(&src[(size_t)j << 12]) : 0.f;
                    float n = (v - mean) * inv;
                    v = fmaxf(fmaf(n, __ldg(&gamma[cib + j]), __ldg(&beta[cib + j])), 0.f);
                    va[j] = ok ? v : 0.f;
                }
            } else {
#pragma unroll
                for (int j = 0; j < 16; j++)
                    va[j] = ok ? __ldg(&src[(size_t)j << 12]) : 0.f;
            }
            uint32_t hp[8], lp[8];
#pragma unroll
            for (int j = 0; j < 8; j++) {
                float a0 = va[2*j], a1 = va[2*j+1];
                float h0 = __bfloat162float(__float2bfloat16_rn(a0));
                float h1 = __bfloat162float(__float2bfloat16_rn(a1));
                hp[j] = pack_bf16(a0, a1);
                lp[j] = pack_bf16(a0 - h0, a1 - h1);
            }
            char* rp = smA + p * SROW + halfk * 32;
            *(uint4*)(rp)           = make_uint4(hp[0], hp[1], hp[2], hp[3]);
            *(uint4*)(rp + 16)      = make_uint4(hp[4], hp[5], hp[6], hp[7]);
            *(uint4*)(rp + 64)      = make_uint4(lp[0], lp[1], lp[2], lp[3]);
            *(uint4*)(rp + 64 + 16) = make_uint4(lp[4], lp[5], lp[6], lp[7]);
        }
        // ---- B: scattered 16 elements, coalesced gmem, conflict-free STS ----
        {
            const float* wc = wb + pos * 128 + ci0;
#pragma unroll
            for (int it = 0; it < 16; it++) {
                int idx = tid + it * 256;          // 4096 = 128 oc x 32 ci
                int oc = idx >> 5, jci = idx & 31;
                float v = __ldg(&wc[(size_t)oc * 1152 + jci]);
                float h = __bfloat162float(__float2bfloat16_rn(v));
                char* rp = smB + oc * SROW + jci * 2;
                *(__nv_bfloat16*)(rp)      = __float2bfloat16_rn(v);
                *(__nv_bfloat16*)(rp + 64) = __float2bfloat16_rn(v - h);
            }
        }
        __syncthreads();

        // ================= compute phase =================
#pragma unroll
        for (int s = 0; s < 2; s++) {
            uint32_t abase = sA + (wm * 64) * SROW + s * 32 + aoff;
            uint32_t bbase = sB + (wn * 32) * SROW + s * 32 + boff;
            uint32_t a[4][4], bh[8], bl[8];
            LDSM4(&bh[0], bbase);                  // oc-tiles 0,1 (hi)
            LDSM4(&bh[4], bbase + 16 * SROW);      // oc-tiles 2,3 (hi)
            LDSM4(&bl[0], bbase + 64);             // lo
            LDSM4(&bl[4], bbase + 16 * SROW + 64);
#pragma unroll
            for (int mi = 0; mi < 4; mi++) LDSM4(a[mi], abase + mi * 16 * SROW);
#pragma unroll
            for (int mi = 0; mi < 4; mi++)
#pragma unroll
                for (int ni = 0; ni < 4; ni++) {
                    MMA16816(d[mi][ni], a[mi], bh[2*ni], bh[2*ni+1]);   // Ah*Bh
                    MMA16816(d[mi][ni], a[mi], bl[2*ni], bl[2*ni+1]);   // Ah*Bl
                }
#pragma unroll
            for (int mi = 0; mi < 4; mi++) LDSM4(a[mi], abase + mi * 16 * SROW + 64);
#pragma unroll
            for (int mi = 0; mi < 4; mi++)
#pragma unroll
                for (int ni = 0; ni < 4; ni++)
                    MMA16816(d[mi][ni], a[mi], bh[2*ni], bh[2*ni+1]);   // Al*Bh
        }
        __syncthreads();
    }

    // ================= epilogue: store raw + GN partial stats =================
    {
        float* ob = out + ((size_t)b << 19) + (y0 << 6);
        float s0 = 0.f, s1 = 0.f, q0 = 0.f, q1 = 0.f;
#pragma unroll
        for (int mi = 0; mi < 4; mi++) {
            int rb = wm * 64 + mi * 16 + (lane >> 2);
#pragma unroll
            for (int ni = 0; ni < 4; ni++) {
                int col = wn * 32 + ni * 8 + (lane & 3) * 2;
#pragma unroll
                for (int rh = 0; rh < 2; rh++) {
                    int r = rb + rh * 8;
                    float v0 = d[mi][ni][rh * 2];
                    float v1 = d[mi][ni][rh * 2 + 1];
                    ob[((size_t)col << 12) + r]       = v0;
                    ob[((size_t)(col + 1) << 12) + r] = v1;
                    if (ni < 2) { s0 += v0 + v1; q0 += v0*v0 + v1*v1; }
                    else        { s1 += v0 + v1; q1 += v0*v0 + v1*v1; }
                }
            }
        }
#pragma unroll
        for (int off = 16; off; off >>= 1) {
            s0 += __shfl_down_sync(0xffffffffu, s0, off);
            q0 += __shfl_down_sync(0xffffffffu, q0, off);
            s1 += __shfl_down_sync(0xffffffffu, s1, off);
            q1 += __shfl_down_sync(0xffffffffu, q1, off);
        }
        if (lane == 0) {
            int g = wn * 2;                      // warp covers oc [wn*32, +32)
            atomicAdd(&st[(b * NG + g) * 2],         s0);
            atomicAdd(&st[(b * NG + g) * 2 + 1],     q0);
            atomicAdd(&st[(b * NG + g + 1) * 2],     s1);
            atomicAdd(&st[(b * NG + g + 1) * 2 + 1], q1);
        }
    }
}

// ---------------- finalize group stats ----------------
template <int PASS>
__global__ void finalize_kernel() {
    const float* st = (PASS == 0) ? g_stats1 : g_stats2;
    float*       mi = (PASS == 0) ? g_mi1    : g_mi2;
    int i = threadIdx.x;                    // 128 = 16 b * 8 g
    float sum = st[i * 2], sq = st[i * 2 + 1];
    const float invN = 1.f / (float)GRPN;
    float mean = sum * invN;
    float var  = sq * invN - mean * mean;
    mi[i * 2]     = mean;
    mi[i * 2 + 1] = rsqrtf(var + EPSV);
}

// ---------------- epilogue: GN2 + residual + ReLU (float4) ----------------
__global__ void epilogue_kernel(const float* __restrict__ x,
                                const float* __restrict__ gamma,
                                const float* __restrict__ beta,
                                float* __restrict__ out) {
    int i4  = blockIdx.x * 256 + threadIdx.x;
    int idx = i4 * 4;
    int c = (idx >> 12) & 127;
    int b = idx >> 19;
    int mg = (b * NG + (c >> 4)) * 2;
    float mean = g_mi2[mg], inv = g_mi2[mg + 1];
    float ga = gamma[c], be = beta[c];
    float4 v  = *(const float4*)&g_buf2[idx];
    float4 xi = *(const float4*)&x[idx];
    float4 r;
    r.x = fmaxf(fmaf((v.x - mean) * inv, ga, be) + xi.x, 0.f);
    r.y = fmaxf(fmaf((v.y - mean) * inv, ga, be) + xi.y, 0.f);
    r.z = fmaxf(fmaf((v.z - mean) * inv, ga, be) + xi.z, 0.f);
    r.w = fmaxf(fmaf((v.w - mean) * inv, ga, be) + xi.w, 0.f);
    *(float4*)&out[idx] = r;
}

// ---------------- launch ----------------
extern "C" void kernel_launch(void* const* d_in, const int* in_sizes, int n_in,
                              void* d_out, int out_size) {
    const float* x   = (const float*)d_in[0];
    const float* z   = (const float*)d_in[1];
    const float* h1w = (const float*)d_in[2];
    const float* h1b = (const float*)d_in[3];
    const float* h2w = (const float*)d_in[4];
    const float* h2b = (const float*)d_in[5];
    const float* g1  = (const float*)d_in[6];
    const float* b1  = (const float*)d_in[7];
    const float* g2  = (const float*)d_in[8];
    const float* b2  = (const float*)d_in[9];
    float* out = (float*)d_out;

    init_stats_kernel<<<1, 256>>>();
    gen_w_kernel<0><<<NW1 / 1024, 256>>>(z, h1w, h1b);
    gen_w_kernel<1><<<NW1 / 1024, 256>>>(z, h2w, h2b);

    dim3 pgrid(BB * CC_, 2);
    permute_w_kernel<<<pgrid, 256>>>();

    dim3 cgrid(32, 16);                     // px-tiles (2 rows each), batch
    conv_mma_kernel<0><<<cgrid, 256>>>(x, g1, b1);
    finalize_kernel<0><<<1, 128>>>();
    conv_mma_kernel<1><<<cgrid, 256>>>(x, g1, b1);
    finalize_kernel<1><<<1, 128>>>();
    epilogue_kernel<<<(BB * IMG) / 1024, 256>>>(x, g2, b2, out);
}

// round 11
// speedup vs baseline: 2.9246x; 1.2028x over previous
#include <cuda_runtime.h>
#include <cuda_bf16.h>
#include <cstdint>

// ---------------- problem constants ----------------
#define BB   16
#define CC_  128
#define ZD   128
#define NG   8
#define EPSV 1e-5f
#define NW1  (CC_*CC_*9)        // 147456
#define IMG  (CC_*64*64)        // 524288
#define GRPN (16*64*64)         // 65536

// ---------------- scratch (alloc-free) ----------------
__device__ float g_w1[BB*NW1];      // hypernet out, [b][oc][ci*9+pos]
__device__ float g_w2[BB*NW1];
// pre-split bf16 weight tiles: [b][cc(36)][r(8: 4 hi, 4 lo)][oc(128)][8 bf16]
__device__ uint4 g_wb1[BB*36*1024];
__device__ uint4 g_wb2[BB*36*1024];
__device__ float g_buf1[BB*IMG];    // conv1 raw out
__device__ float g_bufn[BB*IMG];    // conv1 out, GN1+ReLU applied
__device__ float g_buf2[BB*IMG];    // conv2 raw out
__device__ float g_stats1[BB*NG*2];
__device__ float g_stats2[BB*NG*2];
__device__ float g_mi1[BB*NG*2];
__device__ float g_mi2[BB*NG*2];

// ---------------- helpers (sm_80 baseline PTX) ----------------
__device__ __forceinline__ uint32_t smem_u32(const void* p) {
    uint32_t a;
    asm("{ .reg .u64 t; cvta.to.shared.u64 t, %1; cvt.u32.u64 %0, t; }" : "=r"(a) : "l"(p));
    return a;
}
// pack two f32 -> bf16x2 (lo gets 'lo', hi gets 'hi')
__device__ __forceinline__ uint32_t cvt2(float hi, float lo) {
    uint32_t r; asm("cvt.rn.bf16x2.f32 %0, %1, %2;" : "=r"(r) : "f"(hi), "f"(lo));
    return r;
}

#define LDSM4(r, addr)                                                        \
    asm volatile("ldmatrix.sync.aligned.m8n8.x4.shared.b16 {%0,%1,%2,%3}, [%4];" \
        : "=r"((r)[0]), "=r"((r)[1]), "=r"((r)[2]), "=r"((r)[3]) : "r"(addr))

#define MMA16816(d, a, b0, b1)                                                \
    asm volatile("mma.sync.aligned.m16n8k16.row.col.f32.bf16.bf16.f32 "       \
        "{%0,%1,%2,%3}, {%4,%5,%6,%7}, {%8,%9}, {%0,%1,%2,%3};"               \
        : "+f"((d)[0]), "+f"((d)[1]), "+f"((d)[2]), "+f"((d)[3])              \
        : "r"((a)[0]), "r"((a)[1]), "r"((a)[2]), "r"((a)[3]), "r"(b0), "r"(b1))

// ---------------- init: zero stats ----------------
__global__ void init_stats_kernel() {
    int i = threadIdx.x;
    g_stats1[i] = 0.f;
    g_stats2[i] = 0.f;
}

// ---------------- hypernet weight generation (float4) ----------------
template <int HEAD>
__global__ __launch_bounds__(256) void gen_w_kernel(const float* __restrict__ z,
                                                    const float* __restrict__ hw,
                                                    const float* __restrict__ hb) {
    __shared__ float zs[BB*ZD];
    int tid = threadIdx.x;
    for (int e = tid; e < BB*ZD; e += 256) zs[e] = z[e];
    __syncthreads();

    int idx4 = (blockIdx.x * 256 + tid) * 4;       // grid 144 -> 147456
    float* out = (HEAD == 0) ? g_w1 : g_w2;

    float4 bias = *(const float4*)&hb[idx4];
    float acc[BB][4];
#pragma unroll
    for (int b = 0; b < BB; b++) {
        acc[b][0] = bias.x; acc[b][1] = bias.y; acc[b][2] = bias.z; acc[b][3] = bias.w;
    }
#pragma unroll 2
    for (int zd = 0; zd < ZD; zd++) {
        float4 v = *(const float4*)&hw[(size_t)zd * NW1 + idx4];
#pragma unroll
        for (int b = 0; b < BB; b++) {
            float zv = zs[b * ZD + zd];
            acc[b][0] = fmaf(zv, v.x, acc[b][0]);
            acc[b][1] = fmaf(zv, v.y, acc[b][1]);
            acc[b][2] = fmaf(zv, v.z, acc[b][2]);
            acc[b][3] = fmaf(zv, v.w, acc[b][3]);
        }
    }
#pragma unroll
    for (int b = 0; b < BB; b++)
        *(float4*)&out[(size_t)b * NW1 + idx4] =
            make_float4(acc[b][0], acc[b][1], acc[b][2], acc[b][3]);
}

// ---------------- permute + bf16 hi/lo split into conv tile layout --------
// Block: (ocg of 8 oc, b, head). Loads 8 rows [oc][1152] coalesced, emits
// every chunk's tile piece: dst[(b*36+cc)*1024 + r*128 + oc] (uint4 = 8 bf16).
// r = (0..3 -> hi ci-subchunks, 4..7 -> lo).
__global__ __launch_bounds__(256) void permute_split_kernel() {
    __shared__ float sm[8 * 1152];
    const int ocg  = blockIdx.x;            // 0..15
    const int b    = blockIdx.y;
    const int head = blockIdx.z;
    const float* src = (head ? g_w2 : g_w1) + (size_t)(b * 128 + ocg * 8) * 1152;
    uint4*       dst = (head ? g_wb2 : g_wb1);
    const int tid = threadIdx.x;

    for (int e = tid; e < 9216; e += 256) sm[e] = src[e];
    __syncthreads();

#pragma unroll
    for (int it = 0; it < 9; it++) {
        int e = tid + it * 256;             // < 2304 = 36 cc * 8 r * 8 oc
        int cc  = e >> 6;
        int rem = e & 63;
        int r   = rem >> 3;
        int oc  = rem & 7;
        int ci0 = (cc / 9) * 32 + (r & 3) * 8;
        int pos = cc % 9;
        bool want_lo = (r >> 2);
        uint32_t pk[4];
#pragma unroll
        for (int jp = 0; jp < 4; jp++) {
            float v0 = sm[oc * 1152 + (ci0 + 2*jp)     * 9 + pos];
            float v1 = sm[oc * 1152 + (ci0 + 2*jp + 1) * 9 + pos];
            uint32_t h = cvt2(v1, v0);
            if (want_lo) {
                float h0 = __uint_as_float(h << 16);
                float h1 = __uint_as_float(h & 0xFFFF0000u);
                pk[jp] = cvt2(v1 - h1, v0 - h0);
            } else {
                pk[jp] = h;
            }
        }
        dst[(size_t)(b * 36 + cc) * 1024 + r * 128 + ocg * 8 + oc] =
            make_uint4(pk[0], pk[1], pk[2], pk[3]);
    }
}

// ---------------- mma.sync bf16x3 implicit-GEMM conv ----------------
// CTA: one sample, 128 px (2 rows x 64 cols) x 128 oc. 36 chunks of K=32.
// SMEM rows stride 144B = [32 bf16 hi | 32 bf16 lo | 16B pad].
// Warp grid 2(M)x4(N); warp tile 64px x 32oc; D = Ah*Bh + Ah*Bl + Al*Bh.
#define SROW 144

template <int PASS>
__global__ __launch_bounds__(256, 2) void conv_mma_kernel(
        const float* __restrict__ xin) {
    __shared__ char smA[128 * SROW];
    __shared__ char smB[128 * SROW];

    const float* in  = PASS ? g_bufn  : xin;
    const uint4* wt  = PASS ? g_wb2   : g_wb1;
    float*       out = PASS ? g_buf2  : g_buf1;
    float*       st  = PASS ? g_stats2: g_stats1;

    const int tid  = threadIdx.x;
    const int lane = tid & 31;
    const int wid  = tid >> 5;
    const int wm   = wid & 1;
    const int wn   = wid >> 1;
    const int b    = blockIdx.y;
    const int y0   = blockIdx.x * 2;

    const int p     = tid & 127;          // px row this thread fills (A)
    const int halfk = tid >> 7;           // which 16-ci half (A) / hi-lo (B)
    const int ply   = p >> 6, plx = p & 63;

    const float* inb = in + ((size_t)b << 19);
    const uint4* wbb = wt + ((size_t)b * 36) * 1024;

    const uint32_t sA = smem_u32(smA);
    const uint32_t sB = smem_u32(smB);

    const uint32_t aoff = (uint32_t)(lane & 15) * SROW + ((lane >> 4) << 4);
    const uint32_t boff = (uint32_t)((lane & 7) + ((lane >> 3) & 2) * 4) * SROW
                        + (((lane >> 3) & 1) << 4);

    float d[4][4][4];
#pragma unroll
    for (int mi = 0; mi < 4; mi++)
#pragma unroll
        for (int ni = 0; ni < 4; ni++)
#pragma unroll
            for (int k = 0; k < 4; k++) d[mi][ni][k] = 0.f;

    for (int cc = 0; cc < 36; cc++) {
        const int cig = cc / 9, pos = cc % 9;
        const int ci0 = cig * 32;
        const int dy = pos / 3 - 1, dx = pos % 3 - 1;

        // ---- A: 16 ci for px p, packed cvt split ----
        {
            int gy = y0 + ply + dy, gx = plx + dx;
            bool ok = ((unsigned)gy < 64u) & ((unsigned)gx < 64u);
            const float* src = inb + ((size_t)(ci0 + halfk * 16) << 12)
                             + (gy << 6) + gx;
            float va[16];
#pragma unroll
            for (int j = 0; j < 16; j++)
                va[j] = ok ? src[(size_t)j << 12] : 0.f;
            uint32_t hp[8], lp[8];
#pragma unroll
            for (int j = 0; j < 8; j++) {
                float a0 = va[2*j], a1 = va[2*j+1];
                uint32_t h = cvt2(a1, a0);
                float h0 = __uint_as_float(h << 16);
                float h1 = __uint_as_float(h & 0xFFFF0000u);
                hp[j] = h;
                lp[j] = cvt2(a1 - h1, a0 - h0);
            }
            char* rp = smA + p * SROW + halfk * 32;
            *(uint4*)(rp)           = make_uint4(hp[0], hp[1], hp[2], hp[3]);
            *(uint4*)(rp + 16)      = make_uint4(hp[4], hp[5], hp[6], hp[7]);
            *(uint4*)(rp + 64)      = make_uint4(lp[0], lp[1], lp[2], lp[3]);
            *(uint4*)(rp + 64 + 16) = make_uint4(lp[4], lp[5], lp[6], lp[7]);
        }
        // ---- B: pre-split tiles, 4x LDG.128 + 4x STS.128, conflict-free ----
        {
            const uint4* src = wbb + ((size_t)cc << 10);
            char* rowp = smB + p * SROW;           // p = oc here
#pragma unroll
            for (int j = 0; j < 4; j++) {
                int r = halfk * 4 + j;             // halfk=0 -> hi, 1 -> lo
                uint4 v = src[r * 128 + p];
                *(uint4*)(rowp + (r & 3) * 16 + (r >> 2) * 64) = v;
            }
        }
        __syncthreads();

        // ---- compute ----
#pragma unroll
        for (int s = 0; s < 2; s++) {
            uint32_t abase = sA + (wm * 64) * SROW + s * 32 + aoff;
            uint32_t bbase = sB + (wn * 32) * SROW + s * 32 + boff;
            uint32_t a[4][4], bh[8], bl[8];
            LDSM4(&bh[0], bbase);
            LDSM4(&bh[4], bbase + 16 * SROW);
            LDSM4(&bl[0], bbase + 64);
            LDSM4(&bl[4], bbase + 16 * SROW + 64);
#pragma unroll
            for (int mi = 0; mi < 4; mi++) LDSM4(a[mi], abase + mi * 16 * SROW);
#pragma unroll
            for (int mi = 0; mi < 4; mi++)
#pragma unroll
                for (int ni = 0; ni < 4; ni++) {
                    MMA16816(d[mi][ni], a[mi], bh[2*ni], bh[2*ni+1]);   // Ah*Bh
                    MMA16816(d[mi][ni], a[mi], bl[2*ni], bl[2*ni+1]);   // Ah*Bl
                }
#pragma unroll
            for (int mi = 0; mi < 4; mi++) LDSM4(a[mi], abase + mi * 16 * SROW + 64);
#pragma unroll
            for (int mi = 0; mi < 4; mi++)
#pragma unroll
                for (int ni = 0; ni < 4; ni++)
                    MMA16816(d[mi][ni], a[mi], bh[2*ni], bh[2*ni+1]);   // Al*Bh
        }
        __syncthreads();
    }

    // ---- epilogue: store raw + GN partial stats ----
    {
        float* ob = out + ((size_t)b << 19) + (y0 << 6);
        float s0 = 0.f, s1 = 0.f, q0 = 0.f, q1 = 0.f;
#pragma unroll
        for (int mi = 0; mi < 4; mi++) {
            int rb = wm * 64 + mi * 16 + (lane >> 2);
#pragma unroll
            for (int ni = 0; ni < 4; ni++) {
                int col = wn * 32 + ni * 8 + (lane & 3) * 2;
#pragma unroll
                for (int rh = 0; rh < 2; rh++) {
                    int r = rb + rh * 8;
                    float v0 = d[mi][ni][rh * 2];
                    float v1 = d[mi][ni][rh * 2 + 1];
                    ob[((size_t)col << 12) + r]       = v0;
                    ob[((size_t)(col + 1) << 12) + r] = v1;
                    if (ni < 2) { s0 += v0 + v1; q0 += v0*v0 + v1*v1; }
                    else        { s1 += v0 + v1; q1 += v0*v0 + v1*v1; }
                }
            }
        }
#pragma unroll
        for (int off = 16; off; off >>= 1) {
            s0 += __shfl_down_sync(0xffffffffu, s0, off);
            q0 += __shfl_down_sync(0xffffffffu, q0, off);
            s1 += __shfl_down_sync(0xffffffffu, s1, off);
            q1 += __shfl_down_sync(0xffffffffu, q1, off);
        }
        if (lane == 0) {
            int g = wn * 2;
            atomicAdd(&st[(b * NG + g) * 2],         s0);
            atomicAdd(&st[(b * NG + g) * 2 + 1],     q0);
            atomicAdd(&st[(b * NG + g + 1) * 2],     s1);
            atomicAdd(&st[(b * NG + g + 1) * 2 + 1], q1);
        }
    }
}

// ---------------- finalize group stats ----------------
template <int PASS>
__global__ void finalize_kernel() {
    const float* st = (PASS == 0) ? g_stats1 : g_stats2;
    float*       mi = (PASS == 0) ? g_mi1    : g_mi2;
    int i = threadIdx.x;                    // 128 = 16 b * 8 g
    float sum = st[i * 2], sq = st[i * 2 + 1];
    const float invN = 1.f / (float)GRPN;
    float mean = sum * invN;
    float var  = sq * invN - mean * mean;
    mi[i * 2]     = mean;
    mi[i * 2 + 1] = rsqrtf(var + EPSV);
}

// ---------------- normalize conv1 out: GN1 + ReLU (float4) ----------------
__global__ void normalize1_kernel(const float* __restrict__ gamma,
                                  const float* __restrict__ beta) {
    int idx = (blockIdx.x * 256 + threadIdx.x) * 4;
    int c = (idx >> 12) & 127;
    int b = idx >> 19;
    int mg = (b * NG + (c >> 4)) * 2;
    float mean = g_mi1[mg], inv = g_mi1[mg + 1];
    float ga = gamma[c], be = beta[c];
    float4 v = *(const float4*)&g_buf1[idx];
    float4 r;
    r.x = fmaxf(fmaf((v.x - mean) * inv, ga, be), 0.f);
    r.y = fmaxf(fmaf((v.y - mean) * inv, ga, be), 0.f);
    r.z = fmaxf(fmaf((v.z - mean) * inv, ga, be), 0.f);
    r.w = fmaxf(fmaf((v.w - mean) * inv, ga, be), 0.f);
    *(float4*)&g_bufn[idx] = r;
}

// ---------------- epilogue: GN2 + residual + ReLU (float4) ----------------
__global__ void epilogue_kernel(const float* __restrict__ x,
                                const float* __restrict__ gamma,
                                const float* __restrict__ beta,
                                float* __restrict__ out) {
    int idx = (blockIdx.x * 256 + threadIdx.x) * 4;
    int c = (idx >> 12) & 127;
    int b = idx >> 19;
    int mg = (b * NG + (c >> 4)) * 2;
    float mean = g_mi2[mg], inv = g_mi2[mg + 1];
    float ga = gamma[c], be = beta[c];
    float4 v  = *(const float4*)&g_buf2[idx];
    float4 xi = *(const float4*)&x[idx];
    float4 r;
    r.x = fmaxf(fmaf((v.x - mean) * inv, ga, be) + xi.x, 0.f);
    r.y = fmaxf(fmaf((v.y - mean) * inv, ga, be) + xi.y, 0.f);
    r.z = fmaxf(fmaf((v.z - mean) * inv, ga, be) + xi.z, 0.f);
    r.w = fmaxf(fmaf((v.w - mean) * inv, ga, be) + xi.w, 0.f);
    *(float4*)&out[idx] = r;
}

// ---------------- launch ----------------
extern "C" void kernel_launch(void* const* d_in, const int* in_sizes, int n_in,
                              void* d_out, int out_size) {
    const float* x   = (const float*)d_in[0];
    const float* z   = (const float*)d_in[1];
    const float* h1w = (const float*)d_in[2];
    const float* h1b = (const float*)d_in[3];
    const float* h2w = (const float*)d_in[4];
    const float* h2b = (const float*)d_in[5];
    const float* g1  = (const float*)d_in[6];
    const float* b1  = (const float*)d_in[7];
    const float* g2  = (const float*)d_in[8];
    const float* b2  = (const float*)d_in[9];
    float* out = (float*)d_out;

    init_stats_kernel<<<1, 256>>>();
    gen_w_kernel<0><<<NW1 / 1024, 256>>>(z, h1w, h1b);
    gen_w_kernel<1><<<NW1 / 1024, 256>>>(z, h2w, h2b);

    dim3 pgrid(16, BB, 2);                  // oc-groups, batch, head
    permute_split_kernel<<<pgrid, 256>>>();

    dim3 cgrid(32, 16);                     // px-tiles (2 rows), batch
    conv_mma_kernel<0><<<cgrid, 256>>>(x);
    finalize_kernel<0><<<1, 128>>>();
    normalize1_kernel<<<(BB * IMG) / 1024, 256>>>(g1, b1);
    conv_mma_kernel<1><<<cgrid, 256>>>(x);
    finalize_kernel<1><<<1, 128>>>();
    epilogue_kernel<<<(BB * IMG) / 1024, 256>>>(x, g2, b2, out);
}

// round 13
// speedup vs baseline: 3.3179x; 1.1345x over previous
#include <cuda_runtime.h>
#include <cuda_bf16.h>
#include <cstdint>

// ---------------- problem constants ----------------
#define BB   16
#define CC_  128
#define ZD   128
#define NG   8
#define EPSV 1e-5f
#define NW1  (CC_*CC_*9)        // 147456
#define IMG  (CC_*64*64)        // 524288
#define GRPN (16*64*64)         // 65536

// ---------------- scratch (alloc-free) ----------------
__device__ float g_w1[BB*NW1];      // hypernet out, [b][oc][ci*9+pos]
__device__ float g_w2[BB*NW1];
// B fragments, mma.sync b-frag order:
// [b][cc(36)][wn(4)] x 256 uint4 = [s(2)][hl(2)][grp(2)][lane(32)]
__device__ uint4 g_wf1[BB*36*4*256];
__device__ uint4 g_wf2[BB*36*4*256];
__device__ float g_buf1[BB*IMG];    // conv1 raw out
__device__ float g_bufn[BB*IMG];    // conv1 out, GN1+ReLU applied
__device__ float g_buf2[BB*IMG];    // conv2 raw out
__device__ float g_stats1[BB*NG*2];
__device__ float g_stats2[BB*NG*2];
__device__ float g_mi1[BB*NG*2];
__device__ float g_mi2[BB*NG*2];

// ---------------- helpers (sm_80 baseline PTX) ----------------
__device__ __forceinline__ uint32_t smem_u32(const void* p) {
    uint32_t a;
    asm("{ .reg .u64 t; cvta.to.shared.u64 t, %1; cvt.u32.u64 %0, t; }" : "=r"(a) : "l"(p));
    return a;
}
// pack two f32 -> bf16x2 (low half = 'lo' arg)
__device__ __forceinline__ uint32_t cvt2(float hi, float lo) {
    uint32_t r; asm("cvt.rn.bf16x2.f32 %0, %1, %2;" : "=r"(r) : "f"(hi), "f"(lo));
    return r;
}
__device__ __forceinline__ float blo(uint32_t h) { return __uint_as_float(h << 16); }
__device__ __forceinline__ float bhi(uint32_t h) { return __uint_as_float(h & 0xFFFF0000u); }

#define LDSM4(r, addr)                                                        \
    asm volatile("ldmatrix.sync.aligned.m8n8.x4.shared.b16 {%0,%1,%2,%3}, [%4];" \
        : "=r"((r)[0]), "=r"((r)[1]), "=r"((r)[2]), "=r"((r)[3]) : "r"(addr))

#define MMA16816(d, a, b0, b1)                                                \
    asm volatile("mma.sync.aligned.m16n8k16.row.col.f32.bf16.bf16.f32 "       \
        "{%0,%1,%2,%3}, {%4,%5,%6,%7}, {%8,%9}, {%0,%1,%2,%3};"               \
        : "+f"((d)[0]), "+f"((d)[1]), "+f"((d)[2]), "+f"((d)[3])              \
        : "r"((a)[0]), "r"((a)[1]), "r"((a)[2]), "r"((a)[3]), "r"(b0), "r"(b1))

// ---------------- init: zero stats ----------------
__global__ void init_stats_kernel() {
    int i = threadIdx.x;
    g_stats1[i] = 0.f;
    g_stats2[i] = 0.f;
}

// ---------------- hypernet weight generation (float4) ----------------
template <int HEAD>
__global__ __launch_bounds__(256) void gen_w_kernel(const float* __restrict__ z,
                                                    const float* __restrict__ hw,
                                                    const float* __restrict__ hb) {
    __shared__ float zs[BB*ZD];
    int tid = threadIdx.x;
    for (int e = tid; e < BB*ZD; e += 256) zs[e] = z[e];
    __syncthreads();

    int idx4 = (blockIdx.x * 256 + tid) * 4;       // grid 144 -> 147456
    float* out = (HEAD == 0) ? g_w1 : g_w2;

    float4 bias = *(const float4*)&hb[idx4];
    float acc[BB][4];
#pragma unroll
    for (int b = 0; b < BB; b++) {
        acc[b][0] = bias.x; acc[b][1] = bias.y; acc[b][2] = bias.z; acc[b][3] = bias.w;
    }
#pragma unroll 2
    for (int zd = 0; zd < ZD; zd++) {
        float4 v = *(const float4*)&hw[(size_t)zd * NW1 + idx4];
#pragma unroll
        for (int b = 0; b < BB; b++) {
            float zv = zs[b * ZD + zd];
            acc[b][0] = fmaf(zv, v.x, acc[b][0]);
            acc[b][1] = fmaf(zv, v.y, acc[b][1]);
            acc[b][2] = fmaf(zv, v.z, acc[b][2]);
            acc[b][3] = fmaf(zv, v.w, acc[b][3]);
        }
    }
#pragma unroll
    for (int b = 0; b < BB; b++)
        *(float4*)&out[(size_t)b * NW1 + idx4] =
            make_float4(acc[b][0], acc[b][1], acc[b][2], acc[b][3]);
}

// ---------------- permute to mma b-fragment layout + bf16 hi/lo split ------
// Block: (cig, wn, b*2+head). Stages 32 oc x 288 (32ci x 9pos) floats, emits
// per-lane fragments: dst[((b*36+cc)*4+wn)*256 + s*128 + hl*64 + grp*32 + lane].
__global__ __launch_bounds__(256) void permute_frag_kernel() {
    __shared__ float sm[32 * 288];
    const int cig  = blockIdx.x;            // 0..3
    const int wn   = blockIdx.y;            // 0..3
    const int bz   = blockIdx.z;            // 32 = b*2 + head
    const int b    = bz >> 1;
    const int head = bz & 1;
    const float* src = (head ? g_w2 : g_w1)
                     + (size_t)(b * 128 + wn * 32) * 1152 + cig * 288;
    uint4* dst = (head ? g_wf2 : g_wf1);
    const int tid = threadIdx.x;

    for (int e = tid; e < 32 * 288; e += 256)
        sm[e] = src[(size_t)(e / 288) * 1152 + (e % 288)];
    __syncthreads();

#pragma unroll
    for (int it = 0; it < 9; it++) {
        int e = tid + it * 256;             // < 2304 = 9 pos * 256
        int lane = e & 31;
        int grp  = (e >> 5) & 1;
        int hl   = (e >> 6) & 1;
        int s    = (e >> 7) & 1;
        int pos  = e >> 8;
        int cc   = cig * 9 + pos;
        uint32_t pk[4];
#pragma unroll
        for (int j = 0; j < 2; j++) {
            int n  = (grp * 2 + j) * 8 + (lane >> 2);
            int k0 = s * 16 + (lane & 3) * 2;
            const float* row = &sm[n * 288 + pos];
            float v00 = row[k0 * 9],       v01 = row[(k0 + 1) * 9];
            float v10 = row[(k0 + 8) * 9], v11 = row[(k0 + 9) * 9];
            uint32_t h0 = cvt2(v01, v00);
            uint32_t h1 = cvt2(v11, v10);
            if (hl) {
                pk[j * 2]     = cvt2(v01 - bhi(h0), v00 - blo(h0));
                pk[j * 2 + 1] = cvt2(v11 - bhi(h1), v10 - blo(h1));
            } else {
                pk[j * 2]     = h0;
                pk[j * 2 + 1] = h1;
            }
        }
        dst[(size_t)((b * 36 + cc) * 4 + wn) * 256
            + s * 128 + hl * 64 + grp * 32 + lane] =
            make_uint4(pk[0], pk[1], pk[2], pk[3]);
    }
}

// ---------------- mma.sync bf16x3 implicit-GEMM conv ----------------
// CTA: one sample, 128 px (2 rows x 64 cols) x 128 oc. 4 ci-groups x 9 pos.
// A: padded 4x66 halo strip in smem, built ONCE per ci-group; all 9 positions
//    read it via shifted ldmatrix row addresses. Rows: [32ci hi|32ci lo|pad].
// B: fragment-direct LDG.128 from gmem (pre-packed), no smem, no extra syncs.
// Warp grid 2(M)x4(N); warp tile 64px x 32oc; D = Ah*Bh + Al*Bh + Ah*Bl.
#define SROW 144
#define STRIPR 264                       // 4 * 66

template <int PASS>
__global__ __launch_bounds__(256, 2) void conv_mma_kernel(
        const float* __restrict__ xin) {
    __shared__ char smS[STRIPR * SROW];  // 38016 B

    const float* in  = PASS ? g_bufn  : xin;
    const uint4* wf  = PASS ? g_wf2   : g_wf1;
    float*       out = PASS ? g_buf2  : g_buf1;
    float*       st  = PASS ? g_stats2: g_stats1;

    const int tid  = threadIdx.x;
    const int lane = tid & 31;
    const int wid  = tid >> 5;
    const int wm   = wid & 1;
    const int wn   = wid >> 1;
    const int b    = blockIdx.y;
    const int y0   = blockIdx.x * 2;

    const float* inb = in + ((size_t)b << 19);
    const uint32_t sS = smem_u32(smS);

    // per-lane ldmatrix row base (strip row for dy=dx=0) per mi
    uint32_t abase[4];
#pragma unroll
    for (int mi = 0; mi < 4; mi++) {
        int px  = wm * 64 + mi * 16 + (lane & 15);
        int ply = px >> 6, plx = px & 63;
        abase[mi] = sS + (uint32_t)((ply + 1) * 66 + (plx + 1)) * SROW
                  + ((lane >> 4) << 4);
    }

    float d[4][4][4];
#pragma unroll
    for (int mi = 0; mi < 4; mi++)
#pragma unroll
        for (int ni = 0; ni < 4; ni++)
#pragma unroll
            for (int k = 0; k < 4; k++) d[mi][ni][k] = 0.f;

    for (int cig = 0; cig < 4; cig++) {
        __syncthreads();                 // strip reads of prev cig done
        // ---- build halo strip: 264 rows x 32 ci, hi/lo split ----
        for (int t = tid; t < 528; t += 256) {
            int row = t >> 1, half = t & 1;
            int sy = row / 66, sx = row - sy * 66;
            int gy = y0 + sy - 1, gx = sx - 1;
            bool ok = ((unsigned)gy < 64u) & ((unsigned)gx < 64u);
            const float* src = inb + ((size_t)(cig * 32 + half * 16) << 12)
                             + (gy << 6) + gx;
            float va[16];
#pragma unroll
            for (int j = 0; j < 16; j++)
                va[j] = ok ? src[(size_t)j << 12] : 0.f;
            uint32_t hp[8], lp[8];
#pragma unroll
            for (int j = 0; j < 8; j++) {
                float a0 = va[2*j], a1 = va[2*j+1];
                uint32_t h = cvt2(a1, a0);
                hp[j] = h;
                lp[j] = cvt2(a1 - bhi(h), a0 - blo(h));
            }
            char* rp = smS + row * SROW + half * 32;
            *(uint4*)(rp)           = make_uint4(hp[0], hp[1], hp[2], hp[3]);
            *(uint4*)(rp + 16)      = make_uint4(hp[4], hp[5], hp[6], hp[7]);
            *(uint4*)(rp + 64)      = make_uint4(lp[0], lp[1], lp[2], lp[3]);
            *(uint4*)(rp + 64 + 16) = make_uint4(lp[4], lp[5], lp[6], lp[7]);
        }
        __syncthreads();

        // ---- 9 kernel positions: pure compute from strip + gmem B frags ----
#pragma unroll
        for (int pos = 0; pos < 9; pos++) {
            const int dy = pos / 3 - 1, dx = pos % 3 - 1;
            const int ioff = (dy * 66 + dx) * SROW;
            const int cc = cig * 9 + pos;
            const uint4* wp = wf + (size_t)((b * 36 + cc) * 4 + wn) * 256 + lane;
#pragma unroll
            for (int s = 0; s < 2; s++) {
                uint4 b0 = wp[s * 128];            // bh ni0,ni1
                uint4 b1 = wp[s * 128 + 32];       // bh ni2,ni3
                uint32_t a_hi[4][4], a_lo[4][4];
#pragma unroll
                for (int mi = 0; mi < 4; mi++)
                    LDSM4(a_hi[mi], abase[mi] + ioff + s * 32);
#pragma unroll
                for (int mi = 0; mi < 4; mi++)
                    LDSM4(a_lo[mi], abase[mi] + ioff + s * 32 + 64);
#pragma unroll
                for (int mi = 0; mi < 4; mi++) {   // Ah*Bh
                    MMA16816(d[mi][0], a_hi[mi], b0.x, b0.y);
                    MMA16816(d[mi][1], a_hi[mi], b0.z, b0.w);
                    MMA16816(d[mi][2], a_hi[mi], b1.x, b1.y);
                    MMA16816(d[mi][3], a_hi[mi], b1.z, b1.w);
                }
#pragma unroll
                for (int mi = 0; mi < 4; mi++) {   // Al*Bh
                    MMA16816(d[mi][0], a_lo[mi], b0.x, b0.y);
                    MMA16816(d[mi][1], a_lo[mi], b0.z, b0.w);
                    MMA16816(d[mi][2], a_lo[mi], b1.x, b1.y);
                    MMA16816(d[mi][3], a_lo[mi], b1.z, b1.w);
                }
                b0 = wp[s * 128 + 64];             // bl ni0,ni1
                b1 = wp[s * 128 + 96];             // bl ni2,ni3
#pragma unroll
                for (int mi = 0; mi < 4; mi++) {   // Ah*Bl
                    MMA16816(d[mi][0], a_hi[mi], b0.x, b0.y);
                    MMA16816(d[mi][1], a_hi[mi], b0.z, b0.w);
                    MMA16816(d[mi][2], a_hi[mi], b1.x, b1.y);
                    MMA16816(d[mi][3], a_hi[mi], b1.z, b1.w);
                }
            }
        }
    }

    // ---- epilogue: store raw + GN partial stats ----
    {
        float* ob = out + ((size_t)b << 19) + (y0 << 6);
        float s0 = 0.f, s1 = 0.f, q0 = 0.f, q1 = 0.f;
#pragma unroll
        for (int mi = 0; mi < 4; mi++) {
            int rb = wm * 64 + mi * 16 + (lane >> 2);
#pragma unroll
            for (int ni = 0; ni < 4; ni++) {
                int col = wn * 32 + ni * 8 + (lane & 3) * 2;
#pragma unroll
                for (int rh = 0; rh < 2; rh++) {
                    int r = rb + rh * 8;
                    float v0 = d[mi][ni][rh * 2];
                    float v1 = d[mi][ni][rh * 2 + 1];
                    ob[((size_t)col << 12) + r]       = v0;
                    ob[((size_t)(col + 1) << 12) + r] = v1;
                    if (ni < 2) { s0 += v0 + v1; q0 += v0*v0 + v1*v1; }
                    else        { s1 += v0 + v1; q1 += v0*v0 + v1*v1; }
                }
            }
        }
#pragma unroll
        for (int off = 16; off; off >>= 1) {
            s0 += __shfl_down_sync(0xffffffffu, s0, off);
            q0 += __shfl_down_sync(0xffffffffu, q0, off);
            s1 += __shfl_down_sync(0xffffffffu, s1, off);
            q1 += __shfl_down_sync(0xffffffffu, q1, off);
        }
        if (lane == 0) {
            int g = wn * 2;
            atomicAdd(&st[(b * NG + g) * 2],         s0);
            atomicAdd(&st[(b * NG + g) * 2 + 1],     q0);
            atomicAdd(&st[(b * NG + g + 1) * 2],     s1);
            atomicAdd(&st[(b * NG + g + 1) * 2 + 1], q1);
        }
    }
}

// ---------------- finalize group stats ----------------
template <int PASS>
__global__ void finalize_kernel() {
    const float* st = (PASS == 0) ? g_stats1 : g_stats2;
    float*       mi = (PASS == 0) ? g_mi1    : g_mi2;
    int i = threadIdx.x;                    // 128 = 16 b * 8 g
    float sum = st[i * 2], sq = st[i * 2 + 1];
    const float invN = 1.f / (float)GRPN;
    float mean = sum * invN;
    float var  = sq * invN - mean * mean;
    mi[i * 2]     = mean;
    mi[i * 2 + 1] = rsqrtf(var + EPSV);
}

// ---------------- normalize conv1 out: GN1 + ReLU (float4) ----------------
__global__ void normalize1_kernel(const float* __restrict__ gamma,
                                  const float* __restrict__ beta) {
    int idx = (blockIdx.x * 256 + threadIdx.x) * 4;
    int c = (idx >> 12) & 127;
    int b = idx >> 19;
    int mg = (b * NG + (c >> 4)) * 2;
    float mean = g_mi1[mg], inv = g_mi1[mg + 1];
    float ga = gamma[c], be = beta[c];
    float4 v = *(const float4*)&g_buf1[idx];
    float4 r;
    r.x = fmaxf(fmaf((v.x - mean) * inv, ga, be), 0.f);
    r.y = fmaxf(fmaf((v.y - mean) * inv, ga, be), 0.f);
    r.z = fmaxf(fmaf((v.z - mean) * inv, ga, be), 0.f);
    r.w = fmaxf(fmaf((v.w - mean) * inv, ga, be), 0.f);
    *(float4*)&g_bufn[idx] = r;
}

// ---------------- epilogue: GN2 + residual + ReLU (float4) ----------------
__global__ void epilogue_kernel(const float* __restrict__ x,
                                const float* __restrict__ gamma,
                                const float* __restrict__ beta,
                                float* __restrict__ out) {
    int idx = (blockIdx.x * 256 + threadIdx.x) * 4;
    int c = (idx >> 12) & 127;
    int b = idx >> 19;
    int mg = (b * NG + (c >> 4)) * 2;
    float mean = g_mi2[mg], inv = g_mi2[mg + 1];
    float ga = gamma[c], be = beta[c];
    float4 v  = *(const float4*)&g_buf2[idx];
    float4 xi = *(const float4*)&x[idx];
    float4 r;
    r.x = fmaxf(fmaf((v.x - mean) * inv, ga, be) + xi.x, 0.f);
    r.y = fmaxf(fmaf((v.y - mean) * inv, ga, be) + xi.y, 0.f);
    r.z = fmaxf(fmaf((v.z - mean) * inv, ga, be) + xi.z, 0.f);
    r.w = fmaxf(fmaf((v.w - mean) * inv, ga, be) + xi.w, 0.f);
    *(float4*)&out[idx] = r;
}

// ---------------- launch ----------------
extern "C" void kernel_launch(void* const* d_in, const int* in_sizes, int n_in,
                              void* d_out, int out_size) {
    const float* x   = (const float*)d_in[0];
    const float* z   = (const float*)d_in[1];
    const float* h1w = (const float*)d_in[2];
    const float* h1b = (const float*)d_in[3];
    const float* h2w = (const float*)d_in[4];
    const float* h2b = (const float*)d_in[5];
    const float* g1  = (const float*)d_in[6];
    const float* b1  = (const float*)d_in[7];
    const float* g2  = (const float*)d_in[8];
    const float* b2  = (const float*)d_in[9];
    float* out = (float*)d_out;

    init_stats_kernel<<<1, 256>>>();
    gen_w_kernel<0><<<NW1 / 1024, 256>>>(z, h1w, h1b);
    gen_w_kernel<1><<<NW1 / 1024, 256>>>(z, h2w, h2b);

    dim3 pgrid(4, 4, 32);                   // cig, wn, b*2+head
    permute_frag_kernel<<<pgrid, 256>>>();

    dim3 cgrid(32, 16);                     // px-tiles (2 rows), batch
    conv_mma_kernel<0><<<cgrid, 256>>>(x);
    finalize_kernel<0><<<1, 128>>>();
    normalize1_kernel<<<(BB * IMG) / 1024, 256>>>(g1, b1);
    conv_mma_kernel<1><<<cgrid, 256>>>(x);
    finalize_kernel<1><<<1, 128>>>();
    epilogue_kernel<<<(BB * IMG) / 1024, 256>>>(x, g2, b2, out);
}